// round 1
// baseline (speedup 1.0000x reference)
#include <cuda_runtime.h>
#include <math.h>

#define N_NODES 50000
#define NEDGE   800000
#define IN_DIM  128
#define HID_DIM 256
#define OUT_DIM 128

// ---------------- device scratch (no allocs allowed) ----------------
__device__ int   g_count[N_NODES];
__device__ int   g_row_start[N_NODES + 1];
__device__ int   g_cursor[N_NODES];
__device__ int   g_srcsort[NEDGE];
__device__ float g_agg[(size_t)N_NODES * 256];   // mean-aggregated features (max dim 256)
__device__ float g_h[(size_t)N_NODES * 256];     // layer-1 hidden activations

// ---------------- small utility kernels ----------------
__global__ void zero_int_kernel(int* p, int n) {
    int i = blockIdx.x * blockDim.x + threadIdx.x;
    if (i < n) p[i] = 0;
}

__global__ void copy_int_kernel(int* dst, const int* src, int n) {
    int i = blockIdx.x * blockDim.x + threadIdx.x;
    if (i < n) dst[i] = src[i];
}

// histogram of dst
__global__ void hist_kernel(const int* __restrict__ dst, int* __restrict__ count, int E) {
    int e = blockIdx.x * blockDim.x + threadIdx.x;
    if (e < E) atomicAdd(&count[dst[e]], 1);
}

// single-block exclusive scan (n up to ~64K), 1024 threads
__global__ void scan_kernel(const int* __restrict__ counts, int* __restrict__ row_start, int n) {
    __shared__ int sh[1024];
    __shared__ int carry_s;
    if (threadIdx.x == 0) carry_s = 0;
    __syncthreads();
    for (int base = 0; base < n; base += 1024) {
        int i = base + threadIdx.x;
        int v = (i < n) ? counts[i] : 0;
        sh[threadIdx.x] = v;
        __syncthreads();
        // Hillis-Steele inclusive scan
        for (int off = 1; off < 1024; off <<= 1) {
            int t = (threadIdx.x >= off) ? sh[threadIdx.x - off] : 0;
            __syncthreads();
            sh[threadIdx.x] += t;
            __syncthreads();
        }
        int incl = sh[threadIdx.x];
        int carry = carry_s;
        if (i < n) row_start[i] = carry + incl - v;
        __syncthreads();
        if (threadIdx.x == 1023) carry_s = carry + sh[1023];
        __syncthreads();
    }
    if (threadIdx.x == 0) row_start[n] = carry_s;
}

// scatter src ids into CSR order
__global__ void scatter_kernel(const int* __restrict__ src, const int* __restrict__ dst,
                               int* __restrict__ cursor, int* __restrict__ srcsort, int E) {
    int e = blockIdx.x * blockDim.x + threadIdx.x;
    if (e < E) {
        int d = dst[e];
        int p = atomicAdd(&cursor[d], 1);
        srcsort[p] = src[e];
    }
}

// ---------------- mean aggregation: one block (128 thr) per node ----------------
template <int DIM>
__global__ void aggregate_kernel(const float* __restrict__ x,
                                 const int* __restrict__ row_start,
                                 const int* __restrict__ srcsort,
                                 float* __restrict__ agg) {
    int node = blockIdx.x;
    int t = threadIdx.x;                       // 128 threads
    int s0 = row_start[node];
    int s1 = row_start[node + 1];
    float acc[DIM / 128];
#pragma unroll
    for (int j = 0; j < DIM / 128; j++) acc[j] = 0.f;
    for (int e = s0; e < s1; e++) {
        int s = srcsort[e];
        const float* xr = x + (size_t)s * DIM;
#pragma unroll
        for (int j = 0; j < DIM / 128; j++) acc[j] += xr[j * 128 + t];
    }
    float cnt = (float)max(s1 - s0, 1);
    float* ar = agg + (size_t)node * DIM;
#pragma unroll
    for (int j = 0; j < DIM / 128; j++) ar[j * 128 + t] = acc[j] / cnt;
}

// ---------------- fused SAGE linear: out = tanh(mean@Wl^T + x@Wr^T + b) ----------------
// Treated as one GEMM with K = 2*KHALF over concatenated [mean | x] and [Wl | Wr].
// BM=64, BN=64, BK=16, 256 threads, 4x4 register tile.
template <int KHALF>
__global__ void sage_linear_kernel(const float* __restrict__ A0,   // mean [M, KHALF]
                                   const float* __restrict__ A1,   // x    [M, KHALF]
                                   const float* __restrict__ W0,   // Wl   [H, KHALF]
                                   const float* __restrict__ W1,   // Wr   [H, KHALF]
                                   const float* __restrict__ bias, // [H]
                                   float* __restrict__ out,        // [M, H]
                                   int M, int H) {
    const int BM = 64, BN = 64, BK = 16;
    __shared__ float As[BK][BM];
    __shared__ float Bs[BK][BN];

    int m0 = blockIdx.x * BM;
    int h0 = blockIdx.y * BN;
    int tid = threadIdx.x;        // 256
    int tx = tid & 15;            // output col group (0..15)
    int ty = tid >> 4;            // output row group (0..15)

    int lr = tid >> 2;            // load row 0..63
    int lc = (tid & 3) * 4;       // load col {0,4,8,12}

    float acc[4][4];
#pragma unroll
    for (int i = 0; i < 4; i++)
#pragma unroll
        for (int j = 0; j < 4; j++) acc[i][j] = 0.f;

    for (int kt = 0; kt < 2 * KHALF; kt += BK) {
        const float* A = (kt < KHALF) ? A0 : A1;
        const float* W = (kt < KHALF) ? W0 : W1;
        int k0 = (kt < KHALF) ? kt : (kt - KHALF);

        int m = m0 + lr;
        float4 av = make_float4(0.f, 0.f, 0.f, 0.f);
        if (m < M) av = *(const float4*)&A[(size_t)m * KHALF + k0 + lc];
        float4 wv = *(const float4*)&W[(size_t)(h0 + lr) * KHALF + k0 + lc];

        __syncthreads();  // protect previous iteration's smem reads
        As[lc + 0][lr] = av.x; As[lc + 1][lr] = av.y;
        As[lc + 2][lr] = av.z; As[lc + 3][lr] = av.w;
        Bs[lc + 0][lr] = wv.x; Bs[lc + 1][lr] = wv.y;
        Bs[lc + 2][lr] = wv.z; Bs[lc + 3][lr] = wv.w;
        __syncthreads();

#pragma unroll
        for (int kk = 0; kk < BK; kk++) {
            float4 a = *(const float4*)&As[kk][ty * 4];
            float4 b = *(const float4*)&Bs[kk][tx * 4];
            acc[0][0] += a.x * b.x; acc[0][1] += a.x * b.y; acc[0][2] += a.x * b.z; acc[0][3] += a.x * b.w;
            acc[1][0] += a.y * b.x; acc[1][1] += a.y * b.y; acc[1][2] += a.y * b.z; acc[1][3] += a.y * b.w;
            acc[2][0] += a.z * b.x; acc[2][1] += a.z * b.y; acc[2][2] += a.z * b.z; acc[2][3] += a.z * b.w;
            acc[3][0] += a.w * b.x; acc[3][1] += a.w * b.y; acc[3][2] += a.w * b.z; acc[3][3] += a.w * b.w;
        }
    }

    float4 bv = *(const float4*)&bias[h0 + tx * 4];
#pragma unroll
    for (int i = 0; i < 4; i++) {
        int row = m0 + ty * 4 + i;
        if (row < M) {
            float4 o;
            o.x = tanhf(acc[i][0] + bv.x);
            o.y = tanhf(acc[i][1] + bv.y);
            o.z = tanhf(acc[i][2] + bv.z);
            o.w = tanhf(acc[i][3] + bv.w);
            *(float4*)&out[(size_t)row * H + h0 + tx * 4] = o;
        }
    }
}

// ---------------- host-side orchestration ----------------
static void run_graph(const float* x, const int* edge_index,
                      const float* W1l, const float* b1, const float* W1r,
                      const float* W2l, const float* b2, const float* W2r,
                      float* out,
                      int* count, int* row_start, int* cursor, int* srcsort,
                      float* agg, float* h) {
    const int* src = edge_index;
    const int* dst = edge_index + NEDGE;

    // build CSR (dst -> sorted src list)
    zero_int_kernel<<<(N_NODES + 255) / 256, 256>>>(count, N_NODES);
    hist_kernel<<<(NEDGE + 255) / 256, 256>>>(dst, count, NEDGE);
    scan_kernel<<<1, 1024>>>(count, row_start, N_NODES);
    copy_int_kernel<<<(N_NODES + 255) / 256, 256>>>(cursor, row_start, N_NODES);
    scatter_kernel<<<(NEDGE + 255) / 256, 256>>>(src, dst, cursor, srcsort, NEDGE);

    // layer 1: aggregate x (128 dims), fused linear -> h [N, 256]
    aggregate_kernel<IN_DIM><<<N_NODES, 128>>>(x, row_start, srcsort, agg);
    {
        dim3 grid((N_NODES + 63) / 64, HID_DIM / 64);
        sage_linear_kernel<IN_DIM><<<grid, 256>>>(agg, x, W1l, W1r, b1, h, N_NODES, HID_DIM);
    }

    // layer 2: aggregate h (256 dims), fused linear -> out [N, 128]
    aggregate_kernel<HID_DIM><<<N_NODES, 128>>>(h, row_start, srcsort, agg);
    {
        dim3 grid((N_NODES + 63) / 64, OUT_DIM / 64);
        sage_linear_kernel<HID_DIM><<<grid, 256>>>(agg, h, W2l, W2r, b2, out, N_NODES, OUT_DIM);
    }
}

extern "C" void kernel_launch(void* const* d_in, const int* in_sizes, int n_in,
                              void* d_out, int out_size) {
    (void)in_sizes; (void)n_in; (void)out_size;

    const float* x0  = (const float*)d_in[0];
    const float* x1  = (const float*)d_in[1];
    const int*   ei0 = (const int*)d_in[2];
    const int*   ei1 = (const int*)d_in[3];

    const float* W1l_0 = (const float*)d_in[4];
    const float* b1_0  = (const float*)d_in[5];
    const float* W1r_0 = (const float*)d_in[6];
    const float* W2l_0 = (const float*)d_in[7];
    const float* b2_0  = (const float*)d_in[8];
    const float* W2r_0 = (const float*)d_in[9];

    const float* W1l_1 = (const float*)d_in[10];
    const float* b1_1  = (const float*)d_in[11];
    const float* W1r_1 = (const float*)d_in[12];
    const float* W2l_1 = (const float*)d_in[13];
    const float* b2_1  = (const float*)d_in[14];
    const float* W2r_1 = (const float*)d_in[15];

    float* out = (float*)d_out;

    int *count, *row_start, *cursor, *srcsort;
    float *agg, *h;
    cudaGetSymbolAddress((void**)&count, g_count);
    cudaGetSymbolAddress((void**)&row_start, g_row_start);
    cudaGetSymbolAddress((void**)&cursor, g_cursor);
    cudaGetSymbolAddress((void**)&srcsort, g_srcsort);
    cudaGetSymbolAddress((void**)&agg, g_agg);
    cudaGetSymbolAddress((void**)&h, g_h);

    run_graph(x0, ei0, W1l_0, b1_0, W1r_0, W2l_0, b2_0, W2r_0,
              out, count, row_start, cursor, srcsort, agg, h);
    run_graph(x1, ei1, W1l_1, b1_1, W1r_1, W2l_1, b2_1, W2r_1,
              out + (size_t)N_NODES * OUT_DIM, count, row_start, cursor, srcsort, agg, h);
}

// round 3
// speedup vs baseline: 1.3454x; 1.3454x over previous
#include <cuda_runtime.h>
#include <cuda_bf16.h>
#include <math.h>
#include <stdint.h>

#define N_NODES 50000
#define NEDGE   800000
#define M_TILES ((N_NODES + 127) / 128)

// ================= device scratch (no allocs allowed) =================
__device__ int   g_count[N_NODES];
__device__ int   g_row_start[N_NODES + 1];
__device__ int   g_cursor[N_NODES];
__device__ int   g_srcsort[NEDGE];
__device__ __nv_bfloat16 g_xhi[(size_t)N_NODES * 128];
__device__ __nv_bfloat16 g_xlo[(size_t)N_NODES * 128];
__device__ __nv_bfloat16 g_hhi[(size_t)N_NODES * 256];
__device__ __nv_bfloat16 g_hlo[(size_t)N_NODES * 256];
__device__ __nv_bfloat16 g_ahi[(size_t)N_NODES * 256];
__device__ __nv_bfloat16 g_alo[(size_t)N_NODES * 256];
__device__ __nv_bfloat16 g_wlhi[65536], g_wllo[65536];
__device__ __nv_bfloat16 g_wrhi[65536], g_wrlo[65536];

// ================= helpers =================
__device__ __forceinline__ uint32_t smem_u32(const void* p) {
    uint32_t a;
    asm("{ .reg .u64 t; cvta.to.shared.u64 t, %1; cvt.u32.u64 %0, t; }" : "=r"(a) : "l"(p));
    return a;
}

__device__ __forceinline__ void cp_async16(uint32_t dst, const void* src, bool valid) {
    if (valid) {
        asm volatile("cp.async.cg.shared.global [%0], [%1], 16;" :: "r"(dst), "l"(src));
    } else {
        asm volatile("cp.async.cg.shared.global [%0], [%1], 16, %2;"
                     :: "r"(dst), "l"(src), "r"(0u));
    }
}
#define CP_COMMIT()  asm volatile("cp.async.commit_group;" ::: "memory")
#define CP_WAIT1()   asm volatile("cp.async.wait_group 1;" ::: "memory")

__device__ __forceinline__ void ldsm4(uint32_t* r, uint32_t addr) {
    asm volatile("ldmatrix.sync.aligned.m8n8.x4.shared.b16 {%0,%1,%2,%3}, [%4];"
                 : "=r"(r[0]), "=r"(r[1]), "=r"(r[2]), "=r"(r[3]) : "r"(addr));
}

__device__ __forceinline__ void mma16816(float* d, const uint32_t* a, const uint32_t* b) {
    asm volatile(
        "mma.sync.aligned.m16n8k16.row.col.f32.bf16.bf16.f32 "
        "{%0,%1,%2,%3}, {%4,%5,%6,%7}, {%8,%9}, {%0,%1,%2,%3};"
        : "+f"(d[0]), "+f"(d[1]), "+f"(d[2]), "+f"(d[3])
        : "r"(a[0]), "r"(a[1]), "r"(a[2]), "r"(a[3]), "r"(b[0]), "r"(b[1]));
}

// ================= CSR build =================
__global__ void zero_int_kernel(int* p, int n) {
    int i = blockIdx.x * blockDim.x + threadIdx.x;
    if (i < n) p[i] = 0;
}
__global__ void copy_int_kernel(int* dst, const int* src, int n) {
    int i = blockIdx.x * blockDim.x + threadIdx.x;
    if (i < n) dst[i] = src[i];
}
__global__ void hist_kernel(const int* __restrict__ dst, int* __restrict__ count, int E) {
    int e = blockIdx.x * blockDim.x + threadIdx.x;
    if (e < E) atomicAdd(&count[dst[e]], 1);
}
__global__ void scan_kernel(const int* __restrict__ counts, int* __restrict__ row_start, int n) {
    __shared__ int sh[1024];
    __shared__ int carry_s;
    if (threadIdx.x == 0) carry_s = 0;
    __syncthreads();
    for (int base = 0; base < n; base += 1024) {
        int i = base + threadIdx.x;
        int v = (i < n) ? counts[i] : 0;
        sh[threadIdx.x] = v;
        __syncthreads();
        for (int off = 1; off < 1024; off <<= 1) {
            int t = (threadIdx.x >= off) ? sh[threadIdx.x - off] : 0;
            __syncthreads();
            sh[threadIdx.x] += t;
            __syncthreads();
        }
        int incl = sh[threadIdx.x];
        int carry = carry_s;
        if (i < n) row_start[i] = carry + incl - v;
        __syncthreads();
        if (threadIdx.x == 1023) carry_s = carry + sh[1023];
        __syncthreads();
    }
    if (threadIdx.x == 0) row_start[n] = carry_s;
}
__global__ void scatter_kernel(const int* __restrict__ src, const int* __restrict__ dst,
                               int* __restrict__ cursor, int* __restrict__ srcsort, int E) {
    int e = blockIdx.x * blockDim.x + threadIdx.x;
    if (e < E) {
        int d = dst[e];
        int p = atomicAdd(&cursor[d], 1);
        srcsort[p] = src[e];
    }
}

// ================= fp32 -> bf16 hi/lo split =================
__global__ void split_kernel(const float* __restrict__ in,
                             __nv_bfloat16* __restrict__ hi,
                             __nv_bfloat16* __restrict__ lo, int n) {
    int i = blockIdx.x * blockDim.x + threadIdx.x;
    if (i < n) {
        float v = in[i];
        __nv_bfloat16 h = __float2bfloat16(v);
        hi[i] = h;
        lo[i] = __float2bfloat16(v - __bfloat162float(h));
    }
}

// ================= mean aggregation on bf16 hi/lo pairs =================
template <int DIM>
__global__ void aggregate_pair_kernel(const __nv_bfloat16* __restrict__ xhi,
                                      const __nv_bfloat16* __restrict__ xlo,
                                      const int* __restrict__ row_start,
                                      const int* __restrict__ srcsort,
                                      __nv_bfloat16* __restrict__ ohi,
                                      __nv_bfloat16* __restrict__ olo) {
    int node = blockIdx.x;
    int t = threadIdx.x;  // 128
    int s0 = row_start[node];
    int s1 = row_start[node + 1];
    float acc[DIM / 128];
#pragma unroll
    for (int j = 0; j < DIM / 128; j++) acc[j] = 0.f;
    for (int e = s0; e < s1; e++) {
        int s = srcsort[e];
        size_t base = (size_t)s * DIM;
#pragma unroll
        for (int j = 0; j < DIM / 128; j++) {
            acc[j] += __bfloat162float(xhi[base + j * 128 + t]) +
                      __bfloat162float(xlo[base + j * 128 + t]);
        }
    }
    float inv = 1.0f / (float)max(s1 - s0, 1);
    size_t obase = (size_t)node * DIM;
#pragma unroll
    for (int j = 0; j < DIM / 128; j++) {
        float v = acc[j] * inv;
        __nv_bfloat16 h = __float2bfloat16(v);
        ohi[obase + j * 128 + t] = h;
        olo[obase + j * 128 + t] = __float2bfloat16(v - __bfloat162float(h));
    }
}

// ================= mma.sync split-bf16 fused SAGE linear =================
// C[M, NT] = tanh( [A0 | A1] @ [B0 | B1]^T + bias ), all operands bf16 hi/lo split.
// 3-term split per k-step: Ahi*Bhi + Ahi*Blo + Alo*Bhi.
// CTA tile 128x128, 8 warps (each 64x32), BK=32, 3-stage cp.async pipeline.
// SMEM stage layout: 4 matrices [Ahi, Alo, Bhi, Blo], each 128 rows x 80 bytes.
template <int NT, int KHALF, bool SPLIT>
__global__ void __launch_bounds__(256, 1)
sage_mma_kernel(const __nv_bfloat16* __restrict__ a0hi, const __nv_bfloat16* __restrict__ a0lo,
                const __nv_bfloat16* __restrict__ a1hi, const __nv_bfloat16* __restrict__ a1lo,
                const __nv_bfloat16* __restrict__ b0hi, const __nv_bfloat16* __restrict__ b0lo,
                const __nv_bfloat16* __restrict__ b1hi, const __nv_bfloat16* __restrict__ b1lo,
                const float* __restrict__ bias,
                __nv_bfloat16* __restrict__ ohi, __nv_bfloat16* __restrict__ olo,
                float* __restrict__ ofp, int M) {
    constexpr int NC = 2 * KHALF / 32;          // number of 32-K blocks
    constexpr int MATB = 10240;                 // 128 rows * 80 B
    constexpr int STAGE = 4 * MATB;             // 40960 B

    extern __shared__ char smem[];
    uint32_t sb = smem_u32(smem);

    int tid = threadIdx.x;
    int wid = tid >> 5;
    int lane = tid & 31;
    int wm = wid & 1;        // 0..1 -> 64-row half
    int wn = wid >> 1;       // 0..3 -> 32-col quarter
    int m0 = blockIdx.x * 128;
    int n0 = blockIdx.y * 128;

    // ---- stage issuer ----
    auto issue = [&](int c) {
        int half = (c * 32 >= KHALF) ? 1 : 0;
        int kh0 = c * 32 - half * KHALF;
        const __nv_bfloat16* Ah = half ? a1hi : a0hi;
        const __nv_bfloat16* Al = half ? a1lo : a0lo;
        const __nv_bfloat16* Bh = half ? b1hi : b0hi;
        const __nv_bfloat16* Bl = half ? b1lo : b0lo;
        uint32_t st = sb + (c % 3) * STAGE;
#pragma unroll
        for (int i = 0; i < 8; i++) {
            int idx = i * 256 + tid;
            int mat = idx >> 9;
            int r = (idx >> 2) & 127;
            int ch = idx & 3;
            uint32_t dst = st + mat * MATB + r * 80 + ch * 16;
            if (mat < 2) {
                int m = m0 + r;
                bool valid = (m < M);
                const __nv_bfloat16* src = (mat ? Al : Ah);
                const __nv_bfloat16* p = src + (size_t)(valid ? m : 0) * KHALF + kh0 + ch * 8;
                cp_async16(dst, p, valid);
            } else {
                int n = n0 + r;
                const __nv_bfloat16* src = (mat == 2 ? Bh : Bl);
                cp_async16(dst, src + (size_t)n * KHALF + kh0 + ch * 8, true);
            }
        }
    };

    float acc[4][4][4];
#pragma unroll
    for (int i = 0; i < 4; i++)
#pragma unroll
        for (int j = 0; j < 4; j++)
#pragma unroll
            for (int k = 0; k < 4; k++) acc[i][j][k] = 0.f;

    issue(0); CP_COMMIT();
    if (NC > 1) { issue(1); CP_COMMIT(); }
    else        { CP_COMMIT(); }

    // precomputed intra-stage offsets
    uint32_t a_row = (uint32_t)(wm * 64 + (lane & 15)) * 80 + (lane >> 4) * 16;
    uint32_t b_row = (uint32_t)(wn * 32 + (lane & 7) + ((lane >> 4) << 3)) * 80 +
                     ((lane >> 3) & 1) * 16;

    for (int c = 0; c < NC; c++) {
        CP_WAIT1();
        __syncthreads();
        uint32_t st = sb + (c % 3) * STAGE;
#pragma unroll
        for (int ks = 0; ks < 2; ks++) {
            uint32_t ko = ks * 32;  // 16 bf16 = 32 bytes
            uint32_t Ahf[4][4], Alf[4][4], Bhf[2][4], Blf[2][4];
#pragma unroll
            for (int mt = 0; mt < 4; mt++) {
                uint32_t ar = st + a_row + (uint32_t)mt * (16 * 80) + ko;
                ldsm4(Ahf[mt], ar);
                ldsm4(Alf[mt], ar + MATB);
            }
#pragma unroll
            for (int nt2 = 0; nt2 < 2; nt2++) {
                uint32_t br = st + 2 * MATB + b_row + (uint32_t)nt2 * (16 * 80) + ko;
                ldsm4(Bhf[nt2], br);
                ldsm4(Blf[nt2], br + MATB);
            }
#pragma unroll
            for (int mt = 0; mt < 4; mt++) {
#pragma unroll
                for (int nt = 0; nt < 4; nt++) {
                    const uint32_t* bh = &Bhf[nt >> 1][(nt & 1) * 2];
                    const uint32_t* bl = &Blf[nt >> 1][(nt & 1) * 2];
                    mma16816(acc[mt][nt], Ahf[mt], bh);
                    mma16816(acc[mt][nt], Ahf[mt], bl);
                    mma16816(acc[mt][nt], Alf[mt], bh);
                }
            }
        }
        __syncthreads();
        if (c + 2 < NC) issue(c + 2);
        CP_COMMIT();
    }

    // ---- epilogue: bias + tanh, write from register fragments ----
    int g = lane >> 2, t4 = lane & 3;
#pragma unroll
    for (int mt = 0; mt < 4; mt++) {
#pragma unroll
        for (int nt = 0; nt < 4; nt++) {
            int col = n0 + wn * 32 + nt * 8 + 2 * t4;
            float b0 = bias[col], b1 = bias[col + 1];
#pragma unroll
            for (int hrow = 0; hrow < 2; hrow++) {
                int row = m0 + wm * 64 + mt * 16 + g + hrow * 8;
                if (row < M) {
                    float v0 = tanhf(acc[mt][nt][2 * hrow + 0] + b0);
                    float v1 = tanhf(acc[mt][nt][2 * hrow + 1] + b1);
                    size_t ob = (size_t)row * NT + col;
                    if (SPLIT) {
                        __nv_bfloat16 h0 = __float2bfloat16(v0);
                        __nv_bfloat16 h1 = __float2bfloat16(v1);
                        __nv_bfloat162 ph; ph.x = h0; ph.y = h1;
                        __nv_bfloat162 pl;
                        pl.x = __float2bfloat16(v0 - __bfloat162float(h0));
                        pl.y = __float2bfloat16(v1 - __bfloat162float(h1));
                        *(__nv_bfloat162*)(ohi + ob) = ph;
                        *(__nv_bfloat162*)(olo + ob) = pl;
                    } else {
                        float2 o; o.x = v0; o.y = v1;
                        *(float2*)(ofp + ob) = o;
                    }
                }
            }
        }
    }
}

// ================= host orchestration =================
struct Scratch {
    int *count, *row_start, *cursor, *srcsort;
    __nv_bfloat16 *xhi, *xlo, *hhi, *hlo, *ahi, *alo;
    __nv_bfloat16 *wlhi, *wllo, *wrhi, *wrlo;
};

static void run_graph(const float* x, const int* edge_index,
                      const float* W1l, const float* b1, const float* W1r,
                      const float* W2l, const float* b2, const float* W2r,
                      float* out, const Scratch& S) {
    const int* src = edge_index;
    const int* dst = edge_index + NEDGE;

    // CSR build
    zero_int_kernel<<<(N_NODES + 255) / 256, 256>>>(S.count, N_NODES);
    hist_kernel<<<(NEDGE + 255) / 256, 256>>>(dst, S.count, NEDGE);
    scan_kernel<<<1, 1024>>>(S.count, S.row_start, N_NODES);
    copy_int_kernel<<<(N_NODES + 255) / 256, 256>>>(S.cursor, S.row_start, N_NODES);
    scatter_kernel<<<(NEDGE + 255) / 256, 256>>>(src, dst, S.cursor, S.srcsort, NEDGE);

    // split inputs & layer-1 weights
    split_kernel<<<(N_NODES * 128 + 255) / 256, 256>>>(x, S.xhi, S.xlo, N_NODES * 128);
    split_kernel<<<(256 * 128 + 255) / 256, 256>>>(W1l, S.wlhi, S.wllo, 256 * 128);
    split_kernel<<<(256 * 128 + 255) / 256, 256>>>(W1r, S.wrhi, S.wrlo, 256 * 128);

    // layer 1: agg(x) -> GEMM(K=256) -> h split
    aggregate_pair_kernel<128><<<N_NODES, 128>>>(S.xhi, S.xlo, S.row_start, S.srcsort,
                                                 S.ahi, S.alo);
    {
        dim3 grid(M_TILES, 2);
        sage_mma_kernel<256, 128, true><<<grid, 256, 3 * 40960>>>(
            S.ahi, S.alo, S.xhi, S.xlo, S.wlhi, S.wllo, S.wrhi, S.wrlo,
            b1, S.hhi, S.hlo, nullptr, N_NODES);
    }

    // layer-2 weights
    split_kernel<<<(128 * 256 + 255) / 256, 256>>>(W2l, S.wlhi, S.wllo, 128 * 256);
    split_kernel<<<(128 * 256 + 255) / 256, 256>>>(W2r, S.wrhi, S.wrlo, 128 * 256);

    // layer 2: agg(h) -> GEMM(K=512) -> fp32 out
    aggregate_pair_kernel<256><<<N_NODES, 128>>>(S.hhi, S.hlo, S.row_start, S.srcsort,
                                                 S.ahi, S.alo);
    {
        dim3 grid(M_TILES, 1);
        sage_mma_kernel<128, 256, false><<<grid, 256, 3 * 40960>>>(
            S.ahi, S.alo, S.hhi, S.hlo, S.wlhi, S.wllo, S.wrhi, S.wrlo,
            b2, nullptr, nullptr, out, N_NODES);
    }
}

extern "C" void kernel_launch(void* const* d_in, const int* in_sizes, int n_in,
                              void* d_out, int out_size) {
    (void)in_sizes; (void)n_in; (void)out_size;

    const float* x0  = (const float*)d_in[0];
    const float* x1  = (const float*)d_in[1];
    const int*   ei0 = (const int*)d_in[2];
    const int*   ei1 = (const int*)d_in[3];
    const float* W1l_0 = (const float*)d_in[4];
    const float* b1_0  = (const float*)d_in[5];
    const float* W1r_0 = (const float*)d_in[6];
    const float* W2l_0 = (const float*)d_in[7];
    const float* b2_0  = (const float*)d_in[8];
    const float* W2r_0 = (const float*)d_in[9];
    const float* W1l_1 = (const float*)d_in[10];
    const float* b1_1  = (const float*)d_in[11];
    const float* W1r_1 = (const float*)d_in[12];
    const float* W2l_1 = (const float*)d_in[13];
    const float* b2_1  = (const float*)d_in[14];
    const float* W2r_1 = (const float*)d_in[15];
    float* out = (float*)d_out;

    cudaFuncSetAttribute(sage_mma_kernel<256, 128, true>,
                         cudaFuncAttributeMaxDynamicSharedMemorySize, 3 * 40960);
    cudaFuncSetAttribute(sage_mma_kernel<128, 256, false>,
                         cudaFuncAttributeMaxDynamicSharedMemorySize, 3 * 40960);

    Scratch S;
    cudaGetSymbolAddress((void**)&S.count, g_count);
    cudaGetSymbolAddress((void**)&S.row_start, g_row_start);
    cudaGetSymbolAddress((void**)&S.cursor, g_cursor);
    cudaGetSymbolAddress((void**)&S.srcsort, g_srcsort);
    cudaGetSymbolAddress((void**)&S.xhi, g_xhi);
    cudaGetSymbolAddress((void**)&S.xlo, g_xlo);
    cudaGetSymbolAddress((void**)&S.hhi, g_hhi);
    cudaGetSymbolAddress((void**)&S.hlo, g_hlo);
    cudaGetSymbolAddress((void**)&S.ahi, g_ahi);
    cudaGetSymbolAddress((void**)&S.alo, g_alo);
    cudaGetSymbolAddress((void**)&S.wlhi, g_wlhi);
    cudaGetSymbolAddress((void**)&S.wllo, g_wllo);
    cudaGetSymbolAddress((void**)&S.wrhi, g_wrhi);
    cudaGetSymbolAddress((void**)&S.wrlo, g_wrlo);

    run_graph(x0, ei0, W1l_0, b1_0, W1r_0, W2l_0, b2_0, W2r_0, out, S);
    run_graph(x1, ei1, W1l_1, b1_1, W1r_1, W2l_1, b2_1, W2r_1,
              out + (size_t)N_NODES * 128, S);
}

// round 4
// speedup vs baseline: 1.4583x; 1.0839x over previous
#include <cuda_runtime.h>
#include <cuda_bf16.h>
#include <math.h>
#include <stdint.h>

#define N_NODES 50000
#define NEDGE   800000
#define M_TILES ((N_NODES + 127) / 128)

// ================= device scratch =================
__device__ int   g_count[N_NODES];
__device__ int   g_row_start[N_NODES + 1];
__device__ int   g_cursor[N_NODES];
__device__ int   g_srcsort[NEDGE];
__device__ __nv_bfloat16 g_x0hi[(size_t)N_NODES * 128];
__device__ __nv_bfloat16 g_x0lo[(size_t)N_NODES * 128];
__device__ __nv_bfloat16 g_x1hi[(size_t)N_NODES * 128];
__device__ __nv_bfloat16 g_x1lo[(size_t)N_NODES * 128];
__device__ __nv_bfloat16 g_hhi[(size_t)N_NODES * 256];
__device__ __nv_bfloat16 g_hlo[(size_t)N_NODES * 256];
__device__ __nv_bfloat16 g_ahi[(size_t)N_NODES * 256];
__device__ __nv_bfloat16 g_alo[(size_t)N_NODES * 256];
__device__ __nv_bfloat16 g_whi[8 * 32768];
__device__ __nv_bfloat16 g_wlo[8 * 32768];

// ================= helpers =================
__device__ __forceinline__ uint32_t smem_u32(const void* p) {
    uint32_t a;
    asm("{ .reg .u64 t; cvta.to.shared.u64 t, %1; cvt.u32.u64 %0, t; }" : "=r"(a) : "l"(p));
    return a;
}
__device__ __forceinline__ void cp_async16(uint32_t dst, const void* src, bool valid) {
    if (valid) {
        asm volatile("cp.async.cg.shared.global [%0], [%1], 16;" :: "r"(dst), "l"(src));
    } else {
        asm volatile("cp.async.cg.shared.global [%0], [%1], 16, %2;"
                     :: "r"(dst), "l"(src), "r"(0u));
    }
}
#define CP_COMMIT()  asm volatile("cp.async.commit_group;" ::: "memory")
#define CP_WAIT1()   asm volatile("cp.async.wait_group 1;" ::: "memory")

__device__ __forceinline__ void ldsm4(uint32_t* r, uint32_t addr) {
    asm volatile("ldmatrix.sync.aligned.m8n8.x4.shared.b16 {%0,%1,%2,%3}, [%4];"
                 : "=r"(r[0]), "=r"(r[1]), "=r"(r[2]), "=r"(r[3]) : "r"(addr));
}
__device__ __forceinline__ void mma16816(float* d, const uint32_t* a, const uint32_t* b) {
    asm volatile(
        "mma.sync.aligned.m16n8k16.row.col.f32.bf16.bf16.f32 "
        "{%0,%1,%2,%3}, {%4,%5,%6,%7}, {%8,%9}, {%0,%1,%2,%3};"
        : "+f"(d[0]), "+f"(d[1]), "+f"(d[2]), "+f"(d[3])
        : "r"(a[0]), "r"(a[1]), "r"(a[2]), "r"(a[3]), "r"(b[0]), "r"(b[1]));
}

// ================= upfront split of all fp32 inputs -> bf16 hi/lo =================
struct SplitJobs {
    const float* src[10];
    __nv_bfloat16* hi[10];
    __nv_bfloat16* lo[10];
    int n4cum[11];  // cumulative float4 counts
};

__global__ void split_all_kernel(SplitJobs J) {
    int f = blockIdx.x * blockDim.x + threadIdx.x;
    if (f >= J.n4cum[10]) return;
    int j = 0;
#pragma unroll
    for (int t = 0; t < 10; t++)
        if (f >= J.n4cum[t + 1]) j = t + 1;
    int local = f - J.n4cum[j];
    float4 v = *(const float4*)(J.src[j] + 4 * (size_t)local);
    __nv_bfloat16 hx = __float2bfloat16(v.x);
    __nv_bfloat16 hy = __float2bfloat16(v.y);
    __nv_bfloat16 hz = __float2bfloat16(v.z);
    __nv_bfloat16 hw = __float2bfloat16(v.w);
    __nv_bfloat162 h01, h23, l01, l23;
    h01.x = hx; h01.y = hy; h23.x = hz; h23.y = hw;
    l01.x = __float2bfloat16(v.x - __bfloat162float(hx));
    l01.y = __float2bfloat16(v.y - __bfloat162float(hy));
    l23.x = __float2bfloat16(v.z - __bfloat162float(hz));
    l23.y = __float2bfloat16(v.w - __bfloat162float(hw));
    *(__nv_bfloat162*)(J.hi[j] + 4 * (size_t)local) = h01;
    *(__nv_bfloat162*)(J.hi[j] + 4 * (size_t)local + 2) = h23;
    *(__nv_bfloat162*)(J.lo[j] + 4 * (size_t)local) = l01;
    *(__nv_bfloat162*)(J.lo[j] + 4 * (size_t)local + 2) = l23;
}

// ================= CSR build =================
__global__ void hist_kernel(const int* __restrict__ dst, int* __restrict__ count, int E) {
    int e = blockIdx.x * blockDim.x + threadIdx.x;
    if (e < E) atomicAdd(&count[dst[e]], 1);
}
__global__ void scan_kernel(const int* __restrict__ counts, int* __restrict__ row_start,
                            int* __restrict__ cursor, int n) {
    __shared__ int sh[1024];
    __shared__ int carry_s;
    if (threadIdx.x == 0) carry_s = 0;
    __syncthreads();
    for (int base = 0; base < n; base += 1024) {
        int i = base + threadIdx.x;
        int v = (i < n) ? counts[i] : 0;
        sh[threadIdx.x] = v;
        __syncthreads();
        for (int off = 1; off < 1024; off <<= 1) {
            int t = (threadIdx.x >= off) ? sh[threadIdx.x - off] : 0;
            __syncthreads();
            sh[threadIdx.x] += t;
            __syncthreads();
        }
        int incl = sh[threadIdx.x];
        int carry = carry_s;
        if (i < n) {
            int rs = carry + incl - v;
            row_start[i] = rs;
            cursor[i] = rs;
        }
        __syncthreads();
        if (threadIdx.x == 1023) carry_s = carry + sh[1023];
        __syncthreads();
    }
    if (threadIdx.x == 0) row_start[n] = carry_s;
}
__global__ void scatter_kernel(const int* __restrict__ src, const int* __restrict__ dst,
                               int* __restrict__ cursor, int* __restrict__ srcsort, int E) {
    int e = blockIdx.x * blockDim.x + threadIdx.x;
    if (e < E) {
        int d = dst[e];
        int p = atomicAdd(&cursor[d], 1);
        srcsort[p] = src[e];
    }
}

// ================= mean aggregation on bf16 hi/lo pairs =================
template <int DIM>
__global__ void aggregate_pair_kernel(const __nv_bfloat16* __restrict__ xhi,
                                      const __nv_bfloat16* __restrict__ xlo,
                                      const int* __restrict__ row_start,
                                      const int* __restrict__ srcsort,
                                      __nv_bfloat16* __restrict__ ohi,
                                      __nv_bfloat16* __restrict__ olo) {
    int node = blockIdx.x;
    int t = threadIdx.x;  // 128
    int s0 = row_start[node];
    int s1 = row_start[node + 1];
    float acc[DIM / 128];
#pragma unroll
    for (int j = 0; j < DIM / 128; j++) acc[j] = 0.f;
    for (int e = s0; e < s1; e++) {
        int s = srcsort[e];
        size_t base = (size_t)s * DIM;
#pragma unroll
        for (int j = 0; j < DIM / 128; j++) {
            acc[j] += __bfloat162float(xhi[base + j * 128 + t]) +
                      __bfloat162float(xlo[base + j * 128 + t]);
        }
    }
    float inv = 1.0f / (float)max(s1 - s0, 1);
    size_t obase = (size_t)node * DIM;
#pragma unroll
    for (int j = 0; j < DIM / 128; j++) {
        float v = acc[j] * inv;
        __nv_bfloat16 h = __float2bfloat16(v);
        ohi[obase + j * 128 + t] = h;
        olo[obase + j * 128 + t] = __float2bfloat16(v - __bfloat162float(h));
    }
}

// ================= mma.sync split-bf16 fused SAGE linear =================
// C[128, NT] tile = tanh( [A0|A1] @ [B0|B1]^T + bias ); 3-term hi/lo split.
// 2-stage cp.async double buffer, 2 CTAs/SM.
template <int NT, int KHALF, bool SPLIT>
__global__ void __launch_bounds__(256, 2)
sage_mma_kernel(const __nv_bfloat16* __restrict__ a0hi, const __nv_bfloat16* __restrict__ a0lo,
                const __nv_bfloat16* __restrict__ a1hi, const __nv_bfloat16* __restrict__ a1lo,
                const __nv_bfloat16* __restrict__ b0hi, const __nv_bfloat16* __restrict__ b0lo,
                const __nv_bfloat16* __restrict__ b1hi, const __nv_bfloat16* __restrict__ b1lo,
                const float* __restrict__ bias,
                __nv_bfloat16* __restrict__ ohi, __nv_bfloat16* __restrict__ olo,
                float* __restrict__ ofp, int M) {
    constexpr int NC = 2 * KHALF / 32;
    constexpr int MATB_A = 10240;            // 128 rows * 80 B
    constexpr int MATB_B = NT * 80;
    constexpr int STAGE = 2 * MATB_A + 2 * MATB_B;
    constexpr int WARPS_M = (NT == 128) ? 2 : 4;
    constexpr int ROWS_W = 128 / WARPS_M;
    constexpr int MT = ROWS_W / 16;
    constexpr int ITERS = (256 + 2 * NT) * 4 / 256;

    extern __shared__ char smem[];
    uint32_t sb = smem_u32(smem);

    int tid = threadIdx.x;
    int wid = tid >> 5;
    int lane = tid & 31;
    int wm = wid % WARPS_M;
    int wn = wid / WARPS_M;
    int m0 = blockIdx.x * 128;
    int n0 = blockIdx.y * NT;

    auto issue = [&](int c) {
        int half = (c * 32 >= KHALF) ? 1 : 0;
        int kh0 = c * 32 - half * KHALF;
        const __nv_bfloat16* Ah = half ? a1hi : a0hi;
        const __nv_bfloat16* Al = half ? a1lo : a0lo;
        const __nv_bfloat16* Bh = half ? b1hi : b0hi;
        const __nv_bfloat16* Bl = half ? b1lo : b0lo;
        uint32_t st = sb + (c & 1) * STAGE;
#pragma unroll
        for (int i = 0; i < ITERS; i++) {
            int idx = i * 256 + tid;
            int ch = idx & 3;
            if (idx < 1024) {
                int mat = idx >> 9;
                int r = (idx >> 2) & 127;
                int m = m0 + r;
                bool valid = (m < M);
                const __nv_bfloat16* src = (mat ? Al : Ah);
                const __nv_bfloat16* p = src + (size_t)(valid ? m : 0) * KHALF + kh0 + ch * 8;
                cp_async16(st + mat * MATB_A + r * 80 + ch * 16, p, valid);
            } else {
                int idx2 = idx - 1024;
                int matb = idx2 / (NT * 4);
                int r = (idx2 >> 2) % NT;
                const __nv_bfloat16* src = (matb ? Bl : Bh);
                cp_async16(st + 2 * MATB_A + matb * MATB_B + r * 80 + ch * 16,
                           src + (size_t)(n0 + r) * KHALF + kh0 + ch * 8, true);
            }
        }
    };

    float acc[MT][4][4];
#pragma unroll
    for (int i = 0; i < MT; i++)
#pragma unroll
        for (int j = 0; j < 4; j++)
#pragma unroll
            for (int k = 0; k < 4; k++) acc[i][j][k] = 0.f;

    issue(0); CP_COMMIT();
    issue(1); CP_COMMIT();

    uint32_t a_row = (uint32_t)(wm * ROWS_W + (lane & 15)) * 80 + (lane >> 4) * 16;
    uint32_t b_row = (uint32_t)(wn * 32 + (lane & 7) + ((lane >> 4) << 3)) * 80 +
                     ((lane >> 3) & 1) * 16;

    for (int c = 0; c < NC; c++) {
        CP_WAIT1();
        __syncthreads();
        uint32_t st = sb + (c & 1) * STAGE;
#pragma unroll
        for (int ks = 0; ks < 2; ks++) {
            uint32_t ko = ks * 32;
            uint32_t Ahf[MT][4], Alf[MT][4], Bhf[2][4], Blf[2][4];
#pragma unroll
            for (int mt = 0; mt < MT; mt++) {
                uint32_t ar = st + a_row + (uint32_t)mt * (16 * 80) + ko;
                ldsm4(Ahf[mt], ar);
                ldsm4(Alf[mt], ar + MATB_A);
            }
#pragma unroll
            for (int nt2 = 0; nt2 < 2; nt2++) {
                uint32_t br = st + 2 * MATB_A + b_row + (uint32_t)nt2 * (16 * 80) + ko;
                ldsm4(Bhf[nt2], br);
                ldsm4(Blf[nt2], br + MATB_B);
            }
#pragma unroll
            for (int mt = 0; mt < MT; mt++) {
#pragma unroll
                for (int nt = 0; nt < 4; nt++) {
                    const uint32_t* bh = &Bhf[nt >> 1][(nt & 1) * 2];
                    const uint32_t* bl = &Blf[nt >> 1][(nt & 1) * 2];
                    mma16816(acc[mt][nt], Ahf[mt], bh);
                    mma16816(acc[mt][nt], Ahf[mt], bl);
                    mma16816(acc[mt][nt], Alf[mt], bh);
                }
            }
        }
        __syncthreads();
        if (c + 2 < NC) issue(c + 2);
        CP_COMMIT();
    }

    // ---- epilogue: bias + tanh ----
    int g = lane >> 2, t4 = lane & 3;
#pragma unroll
    for (int mt = 0; mt < MT; mt++) {
#pragma unroll
        for (int nt = 0; nt < 4; nt++) {
            int col = n0 + wn * 32 + nt * 8 + 2 * t4;
            float b0 = bias[col], b1 = bias[col + 1];
#pragma unroll
            for (int hrow = 0; hrow < 2; hrow++) {
                int row = m0 + wm * ROWS_W + mt * 16 + g + hrow * 8;
                if (row < M) {
                    float v0 = tanhf(acc[mt][nt][2 * hrow + 0] + b0);
                    float v1 = tanhf(acc[mt][nt][2 * hrow + 1] + b1);
                    size_t ob = (size_t)row * (SPLIT ? 256 : 128) + col;
                    if (SPLIT) {
                        __nv_bfloat16 h0 = __float2bfloat16(v0);
                        __nv_bfloat16 h1 = __float2bfloat16(v1);
                        __nv_bfloat162 ph; ph.x = h0; ph.y = h1;
                        __nv_bfloat162 pl;
                        pl.x = __float2bfloat16(v0 - __bfloat162float(h0));
                        pl.y = __float2bfloat16(v1 - __bfloat162float(h1));
                        *(__nv_bfloat162*)(ohi + ob) = ph;
                        *(__nv_bfloat162*)(olo + ob) = pl;
                    } else {
                        float2 o; o.x = v0; o.y = v1;
                        *(float2*)(ofp + ob) = o;
                    }
                }
            }
        }
    }
}

// ================= host orchestration =================
struct Scratch {
    int *count, *row_start, *cursor, *srcsort;
    __nv_bfloat16 *hhi, *hlo, *ahi, *alo;
    __nv_bfloat16 *whi, *wlo;
    __nv_bfloat16 *x0hi, *x0lo, *x1hi, *x1lo;
};

static void run_graph(const __nv_bfloat16* xhi, const __nv_bfloat16* xlo,
                      const int* edge_index,
                      const __nv_bfloat16* w1lhi, const __nv_bfloat16* w1llo,
                      const __nv_bfloat16* w1rhi, const __nv_bfloat16* w1rlo,
                      const __nv_bfloat16* w2lhi, const __nv_bfloat16* w2llo,
                      const __nv_bfloat16* w2rhi, const __nv_bfloat16* w2rlo,
                      const float* b1, const float* b2,
                      float* out, const Scratch& S) {
    const int* src = edge_index;
    const int* dst = edge_index + NEDGE;

    cudaMemsetAsync(S.count, 0, N_NODES * sizeof(int));
    hist_kernel<<<(NEDGE + 255) / 256, 256>>>(dst, S.count, NEDGE);
    scan_kernel<<<1, 1024>>>(S.count, S.row_start, S.cursor, N_NODES);
    scatter_kernel<<<(NEDGE + 255) / 256, 256>>>(src, dst, S.cursor, S.srcsort, NEDGE);

    // layer 1
    aggregate_pair_kernel<128><<<N_NODES, 128>>>(xhi, xlo, S.row_start, S.srcsort,
                                                 S.ahi, S.alo);
    {
        dim3 grid(M_TILES, 2);
        sage_mma_kernel<128, 128, true><<<grid, 256, 2 * (2 * 10240 + 2 * 128 * 80)>>>(
            S.ahi, S.alo, xhi, xlo, w1lhi, w1llo, w1rhi, w1rlo,
            b1, S.hhi, S.hlo, nullptr, N_NODES);
    }

    // layer 2
    aggregate_pair_kernel<256><<<N_NODES, 128>>>(S.hhi, S.hlo, S.row_start, S.srcsort,
                                                 S.ahi, S.alo);
    {
        dim3 grid(M_TILES, 2);
        sage_mma_kernel<64, 256, false><<<grid, 256, 2 * (2 * 10240 + 2 * 64 * 80)>>>(
            S.ahi, S.alo, S.hhi, S.hlo, w2lhi, w2llo, w2rhi, w2rlo,
            b2, nullptr, nullptr, out, N_NODES);
    }
}

extern "C" void kernel_launch(void* const* d_in, const int* in_sizes, int n_in,
                              void* d_out, int out_size) {
    (void)in_sizes; (void)n_in; (void)out_size;

    const float* x0  = (const float*)d_in[0];
    const float* x1  = (const float*)d_in[1];
    const int*   ei0 = (const int*)d_in[2];
    const int*   ei1 = (const int*)d_in[3];
    const float* W1l_0 = (const float*)d_in[4];
    const float* b1_0  = (const float*)d_in[5];
    const float* W1r_0 = (const float*)d_in[6];
    const float* W2l_0 = (const float*)d_in[7];
    const float* b2_0  = (const float*)d_in[8];
    const float* W2r_0 = (const float*)d_in[9];
    const float* W1l_1 = (const float*)d_in[10];
    const float* b1_1  = (const float*)d_in[11];
    const float* W1r_1 = (const float*)d_in[12];
    const float* W2l_1 = (const float*)d_in[13];
    const float* b2_1  = (const float*)d_in[14];
    const float* W2r_1 = (const float*)d_in[15];
    float* out = (float*)d_out;

    cudaFuncSetAttribute(sage_mma_kernel<128, 128, true>,
                         cudaFuncAttributeMaxDynamicSharedMemorySize,
                         2 * (2 * 10240 + 2 * 128 * 80));
    cudaFuncSetAttribute(sage_mma_kernel<64, 256, false>,
                         cudaFuncAttributeMaxDynamicSharedMemorySize,
                         2 * (2 * 10240 + 2 * 64 * 80));

    Scratch S;
    cudaGetSymbolAddress((void**)&S.count, g_count);
    cudaGetSymbolAddress((void**)&S.row_start, g_row_start);
    cudaGetSymbolAddress((void**)&S.cursor, g_cursor);
    cudaGetSymbolAddress((void**)&S.srcsort, g_srcsort);
    cudaGetSymbolAddress((void**)&S.hhi, g_hhi);
    cudaGetSymbolAddress((void**)&S.hlo, g_hlo);
    cudaGetSymbolAddress((void**)&S.ahi, g_ahi);
    cudaGetSymbolAddress((void**)&S.alo, g_alo);
    cudaGetSymbolAddress((void**)&S.whi, g_whi);
    cudaGetSymbolAddress((void**)&S.wlo, g_wlo);
    cudaGetSymbolAddress((void**)&S.x0hi, g_x0hi);
    cudaGetSymbolAddress((void**)&S.x0lo, g_x0lo);
    cudaGetSymbolAddress((void**)&S.x1hi, g_x1hi);
    cudaGetSymbolAddress((void**)&S.x1lo, g_x1lo);

    // ---- single upfront split of x0, x1, and all 8 weight matrices ----
    SplitJobs J;
    const float* srcs[10] = {x0, x1, W1l_0, W1r_0, W2l_0, W2r_0, W1l_1, W1r_1, W2l_1, W2r_1};
    int counts[10] = {N_NODES * 128, N_NODES * 128,
                      32768, 32768, 32768, 32768, 32768, 32768, 32768, 32768};
    int cum = 0;
    for (int j = 0; j < 10; j++) {
        J.src[j] = srcs[j];
        if (j == 0)      { J.hi[j] = S.x0hi; J.lo[j] = S.x0lo; }
        else if (j == 1) { J.hi[j] = S.x1hi; J.lo[j] = S.x1lo; }
        else             { J.hi[j] = S.whi + (j - 2) * 32768;
                           J.lo[j] = S.wlo + (j - 2) * 32768; }
        J.n4cum[j] = cum;
        cum += counts[j] / 4;
    }
    J.n4cum[10] = cum;
    split_all_kernel<<<(cum + 255) / 256, 256>>>(J);

    run_graph(S.x0hi, S.x0lo, ei0,
              S.whi + 0 * 32768, S.wlo + 0 * 32768, S.whi + 1 * 32768, S.wlo + 1 * 32768,
              S.whi + 2 * 32768, S.wlo + 2 * 32768, S.whi + 3 * 32768, S.wlo + 3 * 32768,
              b1_0, b2_0, out, S);
    run_graph(S.x1hi, S.x1lo, ei1,
              S.whi + 4 * 32768, S.wlo + 4 * 32768, S.whi + 5 * 32768, S.wlo + 5 * 32768,
              S.whi + 6 * 32768, S.wlo + 6 * 32768, S.whi + 7 * 32768, S.wlo + 7 * 32768,
              b1_1, b2_1, out + (size_t)N_NODES * 128, S);
}

// round 5
// speedup vs baseline: 1.8876x; 1.2944x over previous
#include <cuda_runtime.h>
#include <cuda_bf16.h>
#include <math.h>
#include <stdint.h>

#define N_NODES 50000
#define NTOT    (2 * N_NODES)
#define NEDGE   800000
#define ETOT    (2 * NEDGE)
#define M_TILES ((N_NODES + 127) / 128)   // 391 per graph

// ================= device scratch =================
__device__ int   g_count[NTOT];
__device__ int   g_row_start[NTOT + 1];
__device__ int   g_cursor[NTOT];
__device__ int   g_srcsort[ETOT];
__device__ __nv_bfloat16 g_xhi[(size_t)NTOT * 128];
__device__ __nv_bfloat16 g_xlo[(size_t)NTOT * 128];
__device__ __nv_bfloat16 g_hhi[(size_t)NTOT * 256];
__device__ __nv_bfloat16 g_hlo[(size_t)NTOT * 256];
__device__ __nv_bfloat16 g_ahi[(size_t)NTOT * 256];
__device__ __nv_bfloat16 g_alo[(size_t)NTOT * 256];
__device__ __nv_bfloat16 g_whi[8 * 32768];
__device__ __nv_bfloat16 g_wlo[8 * 32768];

// ================= helpers =================
__device__ __forceinline__ uint32_t smem_u32(const void* p) {
    uint32_t a;
    asm("{ .reg .u64 t; cvta.to.shared.u64 t, %1; cvt.u32.u64 %0, t; }" : "=r"(a) : "l"(p));
    return a;
}
__device__ __forceinline__ void cp_async16(uint32_t dst, const void* src, bool valid) {
    if (valid) {
        asm volatile("cp.async.cg.shared.global [%0], [%1], 16;" :: "r"(dst), "l"(src));
    } else {
        asm volatile("cp.async.cg.shared.global [%0], [%1], 16, %2;"
                     :: "r"(dst), "l"(src), "r"(0u));
    }
}
#define CP_COMMIT()  asm volatile("cp.async.commit_group;" ::: "memory")
#define CP_WAIT1()   asm volatile("cp.async.wait_group 1;" ::: "memory")

__device__ __forceinline__ void ldsm4(uint32_t* r, uint32_t addr) {
    asm volatile("ldmatrix.sync.aligned.m8n8.x4.shared.b16 {%0,%1,%2,%3}, [%4];"
                 : "=r"(r[0]), "=r"(r[1]), "=r"(r[2]), "=r"(r[3]) : "r"(addr));
}
__device__ __forceinline__ void mma16816(float* d, const uint32_t* a, const uint32_t* b) {
    asm volatile(
        "mma.sync.aligned.m16n8k16.row.col.f32.bf16.bf16.f32 "
        "{%0,%1,%2,%3}, {%4,%5,%6,%7}, {%8,%9}, {%0,%1,%2,%3};"
        : "+f"(d[0]), "+f"(d[1]), "+f"(d[2]), "+f"(d[3])
        : "r"(a[0]), "r"(a[1]), "r"(a[2]), "r"(a[3]), "r"(b[0]), "r"(b[1]));
}

// ================= upfront split of all fp32 inputs -> bf16 hi/lo =================
struct SplitJobs {
    const float* src[10];
    __nv_bfloat16* hi[10];
    __nv_bfloat16* lo[10];
    int n4cum[11];
};

__global__ void split_all_kernel(SplitJobs J) {
    int f = blockIdx.x * blockDim.x + threadIdx.x;
    if (f >= J.n4cum[10]) return;
    int j = 0;
#pragma unroll
    for (int t = 0; t < 10; t++)
        if (f >= J.n4cum[t + 1]) j = t + 1;
    int local = f - J.n4cum[j];
    float4 v = *(const float4*)(J.src[j] + 4 * (size_t)local);
    __nv_bfloat16 hx = __float2bfloat16(v.x);
    __nv_bfloat16 hy = __float2bfloat16(v.y);
    __nv_bfloat16 hz = __float2bfloat16(v.z);
    __nv_bfloat16 hw = __float2bfloat16(v.w);
    __nv_bfloat162 h01, h23, l01, l23;
    h01.x = hx; h01.y = hy; h23.x = hz; h23.y = hw;
    l01.x = __float2bfloat16(v.x - __bfloat162float(hx));
    l01.y = __float2bfloat16(v.y - __bfloat162float(hy));
    l23.x = __float2bfloat16(v.z - __bfloat162float(hz));
    l23.y = __float2bfloat16(v.w - __bfloat162float(hw));
    *(__nv_bfloat162*)(J.hi[j] + 4 * (size_t)local) = h01;
    *(__nv_bfloat162*)(J.hi[j] + 4 * (size_t)local + 2) = h23;
    *(__nv_bfloat162*)(J.lo[j] + 4 * (size_t)local) = l01;
    *(__nv_bfloat162*)(J.lo[j] + 4 * (size_t)local + 2) = l23;
}

// ================= merged CSR build over both graphs =================
__global__ void hist_kernel(const int* __restrict__ ei0, const int* __restrict__ ei1,
                            int* __restrict__ count) {
    int e = blockIdx.x * blockDim.x + threadIdx.x;
    if (e >= ETOT) return;
    int d;
    if (e < NEDGE) d = ei0[NEDGE + e];
    else           d = ei1[NEDGE + (e - NEDGE)] + N_NODES;
    atomicAdd(&count[d], 1);
}

// shuffle-based block-strided exclusive scan (1024 threads, one block)
__global__ void scan_kernel(const int* __restrict__ counts, int* __restrict__ row_start,
                            int* __restrict__ cursor, int n) {
    __shared__ int warp_sums[32];
    int tid = threadIdx.x;
    int lane = tid & 31;
    int w = tid >> 5;
    int carry = 0;
    for (int base = 0; base < n; base += 1024) {
        int i = base + tid;
        int v = (i < n) ? counts[i] : 0;
        int x = v;
#pragma unroll
        for (int off = 1; off < 32; off <<= 1) {
            int t = __shfl_up_sync(0xFFFFFFFFu, x, off);
            if (lane >= off) x += t;
        }
        if (lane == 31) warp_sums[w] = x;
        __syncthreads();
        if (w == 0) {
            int s = warp_sums[lane];
#pragma unroll
            for (int off = 1; off < 32; off <<= 1) {
                int t = __shfl_up_sync(0xFFFFFFFFu, s, off);
                if (lane >= off) s += t;
            }
            warp_sums[lane] = s;
        }
        __syncthreads();
        int wpre = (w > 0) ? warp_sums[w - 1] : 0;
        int incl = x + wpre;
        if (i < n) {
            int rs = carry + incl - v;
            row_start[i] = rs;
            cursor[i] = rs;
        }
        int total = warp_sums[31];
        __syncthreads();
        carry += total;
    }
    if (tid == 0) row_start[n] = carry;
}

__global__ void scatter_kernel(const int* __restrict__ ei0, const int* __restrict__ ei1,
                               int* __restrict__ cursor, int* __restrict__ srcsort) {
    int e = blockIdx.x * blockDim.x + threadIdx.x;
    if (e >= ETOT) return;
    int s, d;
    if (e < NEDGE) {
        s = ei0[e];
        d = ei0[NEDGE + e];
    } else {
        int e1 = e - NEDGE;
        s = ei1[e1] + N_NODES;
        d = ei1[NEDGE + e1] + N_NODES;
    }
    int p = atomicAdd(&cursor[d], 1);
    srcsort[p] = s;
}

// ================= mean aggregation (bf16x2 loads, 2 dims/thread) =================
template <int DIM, int NPB>
__global__ void aggregate_pair_kernel(const __nv_bfloat16* __restrict__ xhi,
                                      const __nv_bfloat16* __restrict__ xlo,
                                      const int* __restrict__ row_start,
                                      const int* __restrict__ srcsort,
                                      __nv_bfloat16* __restrict__ ohi,
                                      __nv_bfloat16* __restrict__ olo) {
    constexpr int TPN = DIM / 2;  // threads per node
    int local = threadIdx.x / TPN;
    int t2 = (threadIdx.x % TPN) * 2;
    int node = blockIdx.x * NPB + local;
    int s0 = row_start[node];
    int s1 = row_start[node + 1];
    float ax = 0.f, ay = 0.f;
    for (int e = s0; e < s1; e++) {
        int s = srcsort[e];
        size_t base = (size_t)s * DIM + t2;
        __nv_bfloat162 h = *(const __nv_bfloat162*)(xhi + base);
        __nv_bfloat162 l = *(const __nv_bfloat162*)(xlo + base);
        ax += __bfloat162float(h.x) + __bfloat162float(l.x);
        ay += __bfloat162float(h.y) + __bfloat162float(l.y);
    }
    float inv = 1.0f / (float)max(s1 - s0, 1);
    ax *= inv; ay *= inv;
    __nv_bfloat16 hx = __float2bfloat16(ax);
    __nv_bfloat16 hy = __float2bfloat16(ay);
    __nv_bfloat162 ph, pl;
    ph.x = hx; ph.y = hy;
    pl.x = __float2bfloat16(ax - __bfloat162float(hx));
    pl.y = __float2bfloat16(ay - __bfloat162float(hy));
    size_t ob = (size_t)node * DIM + t2;
    *(__nv_bfloat162*)(ohi + ob) = ph;
    *(__nv_bfloat162*)(olo + ob) = pl;
}

// ================= mma.sync split-bf16 fused SAGE linear (batched graphs) ========
struct GemmW {
    const __nv_bfloat16* b0hi[2];  // Wl hi, per graph
    const __nv_bfloat16* b0lo[2];
    const __nv_bfloat16* b1hi[2];  // Wr hi, per graph
    const __nv_bfloat16* b1lo[2];
    const float* bias[2];
};

template <int NT, int KHALF, bool SPLIT>
__global__ void __launch_bounds__(256, 2)
sage_mma_kernel(const __nv_bfloat16* __restrict__ a0hi, const __nv_bfloat16* __restrict__ a0lo,
                const __nv_bfloat16* __restrict__ a1hi, const __nv_bfloat16* __restrict__ a1lo,
                GemmW W,
                __nv_bfloat16* __restrict__ ohi, __nv_bfloat16* __restrict__ olo,
                float* __restrict__ ofp) {
    constexpr int NC = 2 * KHALF / 32;
    constexpr int MATB_A = 10240;            // 128 rows * 80 B
    constexpr int MATB_B = NT * 80;
    constexpr int STAGE = 2 * MATB_A + 2 * MATB_B;
    constexpr int WARPS_M = (NT == 128) ? 2 : 4;
    constexpr int ROWS_W = 128 / WARPS_M;
    constexpr int MT = ROWS_W / 16;
    constexpr int ITERS = (256 + 2 * NT) * 4 / 256;

    extern __shared__ char smem[];
    uint32_t sb = smem_u32(smem);

    int tid = threadIdx.x;
    int wid = tid >> 5;
    int lane = tid & 31;
    int wm = wid % WARPS_M;
    int wn = wid / WARPS_M;
    int g = blockIdx.z;
    int m0 = g * N_NODES + blockIdx.x * 128;
    int Mlim = (g + 1) * N_NODES;
    int n0 = blockIdx.y * NT;

    const __nv_bfloat16* B0h = W.b0hi[g];
    const __nv_bfloat16* B0l = W.b0lo[g];
    const __nv_bfloat16* B1h = W.b1hi[g];
    const __nv_bfloat16* B1l = W.b1lo[g];
    const float* bias = W.bias[g];

    auto issue = [&](int c) {
        int half = (c * 32 >= KHALF) ? 1 : 0;
        int kh0 = c * 32 - half * KHALF;
        const __nv_bfloat16* Ah = half ? a1hi : a0hi;
        const __nv_bfloat16* Al = half ? a1lo : a0lo;
        const __nv_bfloat16* Bh = half ? B1h : B0h;
        const __nv_bfloat16* Bl = half ? B1l : B0l;
        uint32_t st = sb + (c & 1) * STAGE;
#pragma unroll
        for (int i = 0; i < ITERS; i++) {
            int idx = i * 256 + tid;
            int ch = idx & 3;
            if (idx < 1024) {
                int mat = idx >> 9;
                int r = (idx >> 2) & 127;
                int m = m0 + r;
                bool valid = (m < Mlim);
                const __nv_bfloat16* src = (mat ? Al : Ah);
                const __nv_bfloat16* p = src + (size_t)(valid ? m : 0) * KHALF + kh0 + ch * 8;
                cp_async16(st + mat * MATB_A + r * 80 + ch * 16, p, valid);
            } else {
                int idx2 = idx - 1024;
                int matb = idx2 / (NT * 4);
                int r = (idx2 >> 2) % NT;
                const __nv_bfloat16* src = (matb ? Bl : Bh);
                cp_async16(st + 2 * MATB_A + matb * MATB_B + r * 80 + ch * 16,
                           src + (size_t)(n0 + r) * KHALF + kh0 + ch * 8, true);
            }
        }
    };

    float acc[MT][4][4];
#pragma unroll
    for (int i = 0; i < MT; i++)
#pragma unroll
        for (int j = 0; j < 4; j++)
#pragma unroll
            for (int k = 0; k < 4; k++) acc[i][j][k] = 0.f;

    issue(0); CP_COMMIT();
    issue(1); CP_COMMIT();

    uint32_t a_row = (uint32_t)(wm * ROWS_W + (lane & 15)) * 80 + (lane >> 4) * 16;
    uint32_t b_row = (uint32_t)(wn * 32 + (lane & 7) + ((lane >> 4) << 3)) * 80 +
                     ((lane >> 3) & 1) * 16;

    for (int c = 0; c < NC; c++) {
        CP_WAIT1();
        __syncthreads();
        uint32_t st = sb + (c & 1) * STAGE;
#pragma unroll
        for (int ks = 0; ks < 2; ks++) {
            uint32_t ko = ks * 32;
            uint32_t Ahf[MT][4], Alf[MT][4], Bhf[2][4], Blf[2][4];
#pragma unroll
            for (int mt = 0; mt < MT; mt++) {
                uint32_t ar = st + a_row + (uint32_t)mt * (16 * 80) + ko;
                ldsm4(Ahf[mt], ar);
                ldsm4(Alf[mt], ar + MATB_A);
            }
#pragma unroll
            for (int nt2 = 0; nt2 < 2; nt2++) {
                uint32_t br = st + 2 * MATB_A + b_row + (uint32_t)nt2 * (16 * 80) + ko;
                ldsm4(Bhf[nt2], br);
                ldsm4(Blf[nt2], br + MATB_B);
            }
#pragma unroll
            for (int mt = 0; mt < MT; mt++) {
#pragma unroll
                for (int nt = 0; nt < 4; nt++) {
                    const uint32_t* bh = &Bhf[nt >> 1][(nt & 1) * 2];
                    const uint32_t* bl = &Blf[nt >> 1][(nt & 1) * 2];
                    mma16816(acc[mt][nt], Ahf[mt], bh);
                    mma16816(acc[mt][nt], Ahf[mt], bl);
                    mma16816(acc[mt][nt], Alf[mt], bh);
                }
            }
        }
        __syncthreads();
        if (c + 2 < NC) issue(c + 2);
        CP_COMMIT();
    }

    // ---- epilogue: bias + tanh ----
    int gq = lane >> 2, t4 = lane & 3;
#pragma unroll
    for (int mt = 0; mt < MT; mt++) {
#pragma unroll
        for (int nt = 0; nt < 4; nt++) {
            int col = n0 + wn * 32 + nt * 8 + 2 * t4;
            float b0 = bias[col], b1 = bias[col + 1];
#pragma unroll
            for (int hrow = 0; hrow < 2; hrow++) {
                int row = m0 + wm * ROWS_W + mt * 16 + gq + hrow * 8;
                if (row < Mlim) {
                    float v0 = tanhf(acc[mt][nt][2 * hrow + 0] + b0);
                    float v1 = tanhf(acc[mt][nt][2 * hrow + 1] + b1);
                    size_t ob = (size_t)row * (SPLIT ? 256 : 128) + col;
                    if (SPLIT) {
                        __nv_bfloat16 h0 = __float2bfloat16(v0);
                        __nv_bfloat16 h1 = __float2bfloat16(v1);
                        __nv_bfloat162 ph; ph.x = h0; ph.y = h1;
                        __nv_bfloat162 pl;
                        pl.x = __float2bfloat16(v0 - __bfloat162float(h0));
                        pl.y = __float2bfloat16(v1 - __bfloat162float(h1));
                        *(__nv_bfloat162*)(ohi + ob) = ph;
                        *(__nv_bfloat162*)(olo + ob) = pl;
                    } else {
                        float2 o; o.x = v0; o.y = v1;
                        *(float2*)(ofp + ob) = o;
                    }
                }
            }
        }
    }
}

// ================= host =================
extern "C" void kernel_launch(void* const* d_in, const int* in_sizes, int n_in,
                              void* d_out, int out_size) {
    (void)in_sizes; (void)n_in; (void)out_size;

    const float* x0  = (const float*)d_in[0];
    const float* x1  = (const float*)d_in[1];
    const int*   ei0 = (const int*)d_in[2];
    const int*   ei1 = (const int*)d_in[3];
    const float* W1l_0 = (const float*)d_in[4];
    const float* b1_0  = (const float*)d_in[5];
    const float* W1r_0 = (const float*)d_in[6];
    const float* W2l_0 = (const float*)d_in[7];
    const float* b2_0  = (const float*)d_in[8];
    const float* W2r_0 = (const float*)d_in[9];
    const float* W1l_1 = (const float*)d_in[10];
    const float* b1_1  = (const float*)d_in[11];
    const float* W1r_1 = (const float*)d_in[12];
    const float* W2l_1 = (const float*)d_in[13];
    const float* b2_1  = (const float*)d_in[14];
    const float* W2r_1 = (const float*)d_in[15];
    float* out = (float*)d_out;

    constexpr int SMEM1 = 2 * (2 * 10240 + 2 * 128 * 80);
    constexpr int SMEM2 = 2 * (2 * 10240 + 2 * 64 * 80);
    cudaFuncSetAttribute(sage_mma_kernel<128, 128, true>,
                         cudaFuncAttributeMaxDynamicSharedMemorySize, SMEM1);
    cudaFuncSetAttribute(sage_mma_kernel<64, 256, false>,
                         cudaFuncAttributeMaxDynamicSharedMemorySize, SMEM2);

    int *count, *row_start, *cursor, *srcsort;
    __nv_bfloat16 *xhi, *xlo, *hhi, *hlo, *ahi, *alo, *whi, *wlo;
    cudaGetSymbolAddress((void**)&count, g_count);
    cudaGetSymbolAddress((void**)&row_start, g_row_start);
    cudaGetSymbolAddress((void**)&cursor, g_cursor);
    cudaGetSymbolAddress((void**)&srcsort, g_srcsort);
    cudaGetSymbolAddress((void**)&xhi, g_xhi);
    cudaGetSymbolAddress((void**)&xlo, g_xlo);
    cudaGetSymbolAddress((void**)&hhi, g_hhi);
    cudaGetSymbolAddress((void**)&hlo, g_hlo);
    cudaGetSymbolAddress((void**)&ahi, g_ahi);
    cudaGetSymbolAddress((void**)&alo, g_alo);
    cudaGetSymbolAddress((void**)&whi, g_whi);
    cudaGetSymbolAddress((void**)&wlo, g_wlo);

    // ---- upfront split: x0|x1 into one contiguous [NTOT,128] pair, 8 weights ----
    SplitJobs J;
    const float* srcs[10] = {x0, x1, W1l_0, W1r_0, W2l_0, W2r_0, W1l_1, W1r_1, W2l_1, W2r_1};
    int counts[10] = {N_NODES * 128, N_NODES * 128,
                      32768, 32768, 32768, 32768, 32768, 32768, 32768, 32768};
    int cum = 0;
    for (int j = 0; j < 10; j++) {
        J.src[j] = srcs[j];
        if (j == 0)      { J.hi[j] = xhi;                    J.lo[j] = xlo; }
        else if (j == 1) { J.hi[j] = xhi + (size_t)N_NODES * 128;
                           J.lo[j] = xlo + (size_t)N_NODES * 128; }
        else             { J.hi[j] = whi + (j - 2) * 32768;
                           J.lo[j] = wlo + (j - 2) * 32768; }
        J.n4cum[j] = cum;
        cum += counts[j] / 4;
    }
    J.n4cum[10] = cum;
    split_all_kernel<<<(cum + 255) / 256, 256>>>(J);

    // ---- merged CSR ----
    cudaMemsetAsync(count, 0, NTOT * sizeof(int));
    hist_kernel<<<(ETOT + 255) / 256, 256>>>(ei0, ei1, count);
    scan_kernel<<<1, 1024>>>(count, row_start, cursor, NTOT);
    scatter_kernel<<<(ETOT + 255) / 256, 256>>>(ei0, ei1, cursor, srcsort);

    // weight slots: graph g layer1: Wl=4g+0, Wr=4g+1; layer2: Wl=4g+2, Wr=4g+3
    GemmW W1, W2;
    for (int g = 0; g < 2; g++) {
        W1.b0hi[g] = whi + (4 * g + 0) * 32768; W1.b0lo[g] = wlo + (4 * g + 0) * 32768;
        W1.b1hi[g] = whi + (4 * g + 1) * 32768; W1.b1lo[g] = wlo + (4 * g + 1) * 32768;
        W2.b0hi[g] = whi + (4 * g + 2) * 32768; W2.b0lo[g] = wlo + (4 * g + 2) * 32768;
        W2.b1hi[g] = whi + (4 * g + 3) * 32768; W2.b1lo[g] = wlo + (4 * g + 3) * 32768;
    }
    W1.bias[0] = b1_0; W1.bias[1] = b1_1;
    W2.bias[0] = b2_0; W2.bias[1] = b2_1;

    // ---- layer 1 (both graphs) ----
    aggregate_pair_kernel<128, 2><<<NTOT / 2, 128>>>(xhi, xlo, row_start, srcsort, ahi, alo);
    {
        dim3 grid(M_TILES, 2, 2);
        sage_mma_kernel<128, 128, true><<<grid, 256, SMEM1>>>(
            ahi, alo, xhi, xlo, W1, hhi, hlo, nullptr);
    }

    // ---- layer 2 (both graphs) ----
    aggregate_pair_kernel<256, 1><<<NTOT, 128>>>(hhi, hlo, row_start, srcsort, ahi, alo);
    {
        dim3 grid(M_TILES, 2, 2);
        sage_mma_kernel<64, 256, false><<<grid, 256, SMEM2>>>(
            ahi, alo, hhi, hlo, W2, nullptr, nullptr, out);
    }
}

// round 6
// speedup vs baseline: 2.4161x; 1.2800x over previous
#include <cuda_runtime.h>
#include <cuda_bf16.h>
#include <math.h>
#include <stdint.h>

#define N_NODES 50000
#define NTOT    (2 * N_NODES)
#define NEDGE   800000
#define ETOT    (2 * NEDGE)
#define M_TILES ((N_NODES + 127) / 128)   // 391 per graph

// ================= device scratch =================
__device__ int   g_count[NTOT];
__device__ int   g_row_start[NTOT + 1];
__device__ int   g_cursor[NTOT];
__device__ int   g_srcsort[ETOT];
__device__ __nv_bfloat16 g_xhi[(size_t)NTOT * 128];
__device__ __nv_bfloat16 g_xlo[(size_t)NTOT * 128];
__device__ __nv_bfloat16 g_hhi[(size_t)NTOT * 256];
__device__ __nv_bfloat16 g_hlo[(size_t)NTOT * 256];
__device__ __nv_bfloat16 g_ahi[(size_t)NTOT * 128];
__device__ __nv_bfloat16 g_alo[(size_t)NTOT * 128];
__device__ float g_pq[(size_t)NTOT * 256];
__device__ __nv_bfloat16 g_whi[8 * 32768];
__device__ __nv_bfloat16 g_wlo[8 * 32768];

// ================= helpers =================
__device__ __forceinline__ uint32_t smem_u32(const void* p) {
    uint32_t a;
    asm("{ .reg .u64 t; cvta.to.shared.u64 t, %1; cvt.u32.u64 %0, t; }" : "=r"(a) : "l"(p));
    return a;
}
__device__ __forceinline__ void cp_async16(uint32_t dst, const void* src, bool valid) {
    if (valid) {
        asm volatile("cp.async.cg.shared.global [%0], [%1], 16;" :: "r"(dst), "l"(src));
    } else {
        asm volatile("cp.async.cg.shared.global [%0], [%1], 16, %2;"
                     :: "r"(dst), "l"(src), "r"(0u));
    }
}
#define CP_COMMIT()  asm volatile("cp.async.commit_group;" ::: "memory")
#define CP_WAIT1()   asm volatile("cp.async.wait_group 1;" ::: "memory")

__device__ __forceinline__ void ldsm4(uint32_t* r, uint32_t addr) {
    asm volatile("ldmatrix.sync.aligned.m8n8.x4.shared.b16 {%0,%1,%2,%3}, [%4];"
                 : "=r"(r[0]), "=r"(r[1]), "=r"(r[2]), "=r"(r[3]) : "r"(addr));
}
__device__ __forceinline__ void mma16816(float* d, const uint32_t* a, const uint32_t* b) {
    asm volatile(
        "mma.sync.aligned.m16n8k16.row.col.f32.bf16.bf16.f32 "
        "{%0,%1,%2,%3}, {%4,%5,%6,%7}, {%8,%9}, {%0,%1,%2,%3};"
        : "+f"(d[0]), "+f"(d[1]), "+f"(d[2]), "+f"(d[3])
        : "r"(a[0]), "r"(a[1]), "r"(a[2]), "r"(a[3]), "r"(b[0]), "r"(b[1]));
}

// fast tanh: 1 - 2/(e^{2x}+1). MUFU.EX2 + MUFU.RCP, ~1e-6 rel err, saturates correctly.
__device__ __forceinline__ float fast_tanh(float x) {
    float e = __expf(2.0f * x);
    return 1.0f - __fdividef(2.0f, e + 1.0f);
}

// ================= upfront split of all fp32 inputs -> bf16 hi/lo =================
struct SplitJobs {
    const float* src[10];
    __nv_bfloat16* hi[10];
    __nv_bfloat16* lo[10];
    int n4cum[11];
};

__global__ void split_all_kernel(SplitJobs J) {
    int f = blockIdx.x * blockDim.x + threadIdx.x;
    if (f >= J.n4cum[10]) return;
    int j = 0;
#pragma unroll
    for (int t = 0; t < 10; t++)
        if (f >= J.n4cum[t + 1]) j = t + 1;
    int local = f - J.n4cum[j];
    float4 v = *(const float4*)(J.src[j] + 4 * (size_t)local);
    __nv_bfloat16 hx = __float2bfloat16(v.x);
    __nv_bfloat16 hy = __float2bfloat16(v.y);
    __nv_bfloat16 hz = __float2bfloat16(v.z);
    __nv_bfloat16 hw = __float2bfloat16(v.w);
    __nv_bfloat162 h01, h23, l01, l23;
    h01.x = hx; h01.y = hy; h23.x = hz; h23.y = hw;
    l01.x = __float2bfloat16(v.x - __bfloat162float(hx));
    l01.y = __float2bfloat16(v.y - __bfloat162float(hy));
    l23.x = __float2bfloat16(v.z - __bfloat162float(hz));
    l23.y = __float2bfloat16(v.w - __bfloat162float(hw));
    *(__nv_bfloat162*)(J.hi[j] + 4 * (size_t)local) = h01;
    *(__nv_bfloat162*)(J.hi[j] + 4 * (size_t)local + 2) = h23;
    *(__nv_bfloat162*)(J.lo[j] + 4 * (size_t)local) = l01;
    *(__nv_bfloat162*)(J.lo[j] + 4 * (size_t)local + 2) = l23;
}

// ================= merged CSR build over both graphs =================
__global__ void hist_kernel(const int* __restrict__ ei0, const int* __restrict__ ei1,
                            int* __restrict__ count) {
    int e = blockIdx.x * blockDim.x + threadIdx.x;
    if (e >= ETOT) return;
    int d;
    if (e < NEDGE) d = ei0[NEDGE + e];
    else           d = ei1[NEDGE + (e - NEDGE)] + N_NODES;
    atomicAdd(&count[d], 1);
}

__global__ void scan_kernel(const int* __restrict__ counts, int* __restrict__ row_start,
                            int* __restrict__ cursor, int n) {
    __shared__ int warp_sums[32];
    int tid = threadIdx.x;
    int lane = tid & 31;
    int w = tid >> 5;
    int carry = 0;
    for (int base = 0; base < n; base += 1024) {
        int i = base + tid;
        int v = (i < n) ? counts[i] : 0;
        int x = v;
#pragma unroll
        for (int off = 1; off < 32; off <<= 1) {
            int t = __shfl_up_sync(0xFFFFFFFFu, x, off);
            if (lane >= off) x += t;
        }
        if (lane == 31) warp_sums[w] = x;
        __syncthreads();
        if (w == 0) {
            int s = warp_sums[lane];
#pragma unroll
            for (int off = 1; off < 32; off <<= 1) {
                int t = __shfl_up_sync(0xFFFFFFFFu, s, off);
                if (lane >= off) s += t;
            }
            warp_sums[lane] = s;
        }
        __syncthreads();
        int wpre = (w > 0) ? warp_sums[w - 1] : 0;
        int incl = x + wpre;
        if (i < n) {
            int rs = carry + incl - v;
            row_start[i] = rs;
            cursor[i] = rs;
        }
        int total = warp_sums[31];
        __syncthreads();
        carry += total;
    }
    if (tid == 0) row_start[n] = carry;
}

__global__ void scatter_kernel(const int* __restrict__ ei0, const int* __restrict__ ei1,
                               int* __restrict__ cursor, int* __restrict__ srcsort) {
    int e = blockIdx.x * blockDim.x + threadIdx.x;
    if (e >= ETOT) return;
    int s, d;
    if (e < NEDGE) {
        s = ei0[e];
        d = ei0[NEDGE + e];
    } else {
        int e1 = e - NEDGE;
        s = ei1[e1] + N_NODES;
        d = ei1[NEDGE + e1] + N_NODES;
    }
    int p = atomicAdd(&cursor[d], 1);
    srcsort[p] = s;
}

// ================= layer-1 mean aggregation (bf16 pairs, 128 dims) =================
__global__ void aggregate1_kernel(const __nv_bfloat16* __restrict__ xhi,
                                  const __nv_bfloat16* __restrict__ xlo,
                                  const int* __restrict__ row_start,
                                  const int* __restrict__ srcsort,
                                  __nv_bfloat16* __restrict__ ohi,
                                  __nv_bfloat16* __restrict__ olo) {
    int local = threadIdx.x >> 6;            // 2 nodes per 128-thread block
    int t2 = (threadIdx.x & 63) * 2;
    int node = blockIdx.x * 2 + local;
    int s0 = row_start[node];
    int s1 = row_start[node + 1];
    float ax = 0.f, ay = 0.f;
    for (int e = s0; e < s1; e++) {
        int s = srcsort[e];
        size_t base = (size_t)s * 128 + t2;
        __nv_bfloat162 h = *(const __nv_bfloat162*)(xhi + base);
        __nv_bfloat162 l = *(const __nv_bfloat162*)(xlo + base);
        ax += __bfloat162float(h.x) + __bfloat162float(l.x);
        ay += __bfloat162float(h.y) + __bfloat162float(l.y);
    }
    float inv = 1.0f / (float)max(s1 - s0, 1);
    ax *= inv; ay *= inv;
    __nv_bfloat16 hx = __float2bfloat16(ax);
    __nv_bfloat16 hy = __float2bfloat16(ay);
    __nv_bfloat162 ph, pl;
    ph.x = hx; ph.y = hy;
    pl.x = __float2bfloat16(ax - __bfloat162float(hx));
    pl.y = __float2bfloat16(ay - __bfloat162float(hy));
    size_t ob = (size_t)node * 128 + t2;
    *(__nv_bfloat162*)(ohi + ob) = ph;
    *(__nv_bfloat162*)(olo + ob) = pl;
}

// ================= layer-2 fused aggregation + epilogue =================
// out[node,c] = tanh( mean_src p[src,c] + q[node,c] + b[c] ), p=pq[:,0:128], q=pq[:,128:256]
__global__ void agg_fuse2_kernel(const float* __restrict__ pq,
                                 const int* __restrict__ row_start,
                                 const int* __restrict__ srcsort,
                                 const float* __restrict__ b2_0,
                                 const float* __restrict__ b2_1,
                                 float* __restrict__ out) {
    int local = threadIdx.x >> 5;            // 4 nodes per 128-thread block
    int t4 = (threadIdx.x & 31) * 4;
    int node = blockIdx.x * 4 + local;
    int s0 = row_start[node];
    int s1 = row_start[node + 1];
    float4 acc = make_float4(0.f, 0.f, 0.f, 0.f);
    for (int e = s0; e < s1; e++) {
        float4 v = *(const float4*)(pq + (size_t)srcsort[e] * 256 + t4);
        acc.x += v.x; acc.y += v.y; acc.z += v.z; acc.w += v.w;
    }
    float inv = 1.0f / (float)max(s1 - s0, 1);
    const float* b = (node < N_NODES) ? b2_0 : b2_1;
    float4 q = *(const float4*)(pq + (size_t)node * 256 + 128 + t4);
    float4 bb = *(const float4*)(b + t4);
    float4 o;
    o.x = fast_tanh(acc.x * inv + q.x + bb.x);
    o.y = fast_tanh(acc.y * inv + q.y + bb.y);
    o.z = fast_tanh(acc.z * inv + q.z + bb.z);
    o.w = fast_tanh(acc.w * inv + q.w + bb.w);
    *(float4*)(out + (size_t)node * 128 + t4) = o;
}

// ================= mma.sync split-bf16 GEMM (batched graphs) =================
// C[128, NT] tile of [A0|A1] @ B^T ; 3-term hi/lo split; per-(y,g) B selection.
struct GemmW {
    const __nv_bfloat16* b0hi[2][2];  // [y][g]: first K-half weights
    const __nv_bfloat16* b0lo[2][2];
    const __nv_bfloat16* b1hi[2][2];  // [y][g]: second K-half weights
    const __nv_bfloat16* b1lo[2][2];
    const float* bias[2];
};

template <int NT, int KHALF, int ASTRIDE, int BSTRIDE, int BOFF, bool SPLIT>
__global__ void __launch_bounds__(256, 2)
sage_mma_kernel(const __nv_bfloat16* __restrict__ a0hi, const __nv_bfloat16* __restrict__ a0lo,
                const __nv_bfloat16* __restrict__ a1hi, const __nv_bfloat16* __restrict__ a1lo,
                GemmW W,
                __nv_bfloat16* __restrict__ ohi, __nv_bfloat16* __restrict__ olo,
                float* __restrict__ ofp) {
    constexpr int NC = 2 * KHALF / 32;
    constexpr int MATB_A = 10240;            // 128 rows * 80 B
    constexpr int MATB_B = NT * 80;
    constexpr int STAGE = 2 * MATB_A + 2 * MATB_B;
    constexpr int WARPS_M = 2;
    constexpr int ROWS_W = 64;
    constexpr int MT = 4;
    constexpr int ITERS = (256 + 2 * NT) * 4 / 256;

    extern __shared__ char smem[];
    uint32_t sb = smem_u32(smem);

    int tid = threadIdx.x;
    int wid = tid >> 5;
    int lane = tid & 31;
    int wm = wid % WARPS_M;
    int wn = wid / WARPS_M;
    int y = blockIdx.y;
    int g = blockIdx.z;
    int m0 = g * N_NODES + blockIdx.x * 128;
    int Mlim = (g + 1) * N_NODES;
    int n0 = y * NT;         // output column offset
    int bn0 = y * BOFF;      // B row offset (0 when B matrix differs per y)

    const __nv_bfloat16* B0h = W.b0hi[y][g];
    const __nv_bfloat16* B0l = W.b0lo[y][g];
    const __nv_bfloat16* B1h = W.b1hi[y][g];
    const __nv_bfloat16* B1l = W.b1lo[y][g];

    auto issue = [&](int c) {
        int half = (c * 32 >= KHALF) ? 1 : 0;
        int kh0 = c * 32 - half * KHALF;
        const __nv_bfloat16* Ah = half ? a1hi : a0hi;
        const __nv_bfloat16* Al = half ? a1lo : a0lo;
        const __nv_bfloat16* Bh = half ? B1h : B0h;
        const __nv_bfloat16* Bl = half ? B1l : B0l;
        uint32_t st = sb + (c & 1) * STAGE;
#pragma unroll
        for (int i = 0; i < ITERS; i++) {
            int idx = i * 256 + tid;
            int ch = idx & 3;
            if (idx < 1024) {
                int mat = idx >> 9;
                int r = (idx >> 2) & 127;
                int m = m0 + r;
                bool valid = (m < Mlim);
                const __nv_bfloat16* src = (mat ? Al : Ah);
                const __nv_bfloat16* p = src + (size_t)(valid ? m : 0) * ASTRIDE + kh0 + ch * 8;
                cp_async16(st + mat * MATB_A + r * 80 + ch * 16, p, valid);
            } else {
                int idx2 = idx - 1024;
                int matb = idx2 / (NT * 4);
                int r = (idx2 >> 2) % NT;
                const __nv_bfloat16* src = (matb ? Bl : Bh);
                cp_async16(st + 2 * MATB_A + matb * MATB_B + r * 80 + ch * 16,
                           src + (size_t)(bn0 + r) * BSTRIDE + kh0 + ch * 8, true);
            }
        }
    };

    float acc[MT][4][4];
#pragma unroll
    for (int i = 0; i < MT; i++)
#pragma unroll
        for (int j = 0; j < 4; j++)
#pragma unroll
            for (int k = 0; k < 4; k++) acc[i][j][k] = 0.f;

    issue(0); CP_COMMIT();
    issue(1); CP_COMMIT();

    uint32_t a_row = (uint32_t)(wm * ROWS_W + (lane & 15)) * 80 + (lane >> 4) * 16;
    uint32_t b_row = (uint32_t)(wn * 32 + (lane & 7) + ((lane >> 4) << 3)) * 80 +
                     ((lane >> 3) & 1) * 16;

    for (int c = 0; c < NC; c++) {
        CP_WAIT1();
        __syncthreads();
        uint32_t st = sb + (c & 1) * STAGE;
#pragma unroll
        for (int ks = 0; ks < 2; ks++) {
            uint32_t ko = ks * 32;
            uint32_t Ahf[MT][4], Alf[MT][4], Bhf[2][4], Blf[2][4];
#pragma unroll
            for (int mt = 0; mt < MT; mt++) {
                uint32_t ar = st + a_row + (uint32_t)mt * (16 * 80) + ko;
                ldsm4(Ahf[mt], ar);
                ldsm4(Alf[mt], ar + MATB_A);
            }
#pragma unroll
            for (int nt2 = 0; nt2 < 2; nt2++) {
                uint32_t br = st + 2 * MATB_A + b_row + (uint32_t)nt2 * (16 * 80) + ko;
                ldsm4(Bhf[nt2], br);
                ldsm4(Blf[nt2], br + MATB_B);
            }
#pragma unroll
            for (int mt = 0; mt < MT; mt++) {
#pragma unroll
                for (int nt = 0; nt < 4; nt++) {
                    const uint32_t* bh = &Bhf[nt >> 1][(nt & 1) * 2];
                    const uint32_t* bl = &Blf[nt >> 1][(nt & 1) * 2];
                    mma16816(acc[mt][nt], Ahf[mt], bh);
                    mma16816(acc[mt][nt], Ahf[mt], bl);
                    mma16816(acc[mt][nt], Alf[mt], bh);
                }
            }
        }
        __syncthreads();
        if (c + 2 < NC) issue(c + 2);
        CP_COMMIT();
    }

    // ---- epilogue ----
    int gq = lane >> 2, t4 = lane & 3;
    const float* bias = SPLIT ? W.bias[g] : nullptr;
#pragma unroll
    for (int mt = 0; mt < MT; mt++) {
#pragma unroll
        for (int nt = 0; nt < 4; nt++) {
            int col = n0 + wn * 32 + nt * 8 + 2 * t4;
            float b0 = SPLIT ? bias[col] : 0.f;
            float b1 = SPLIT ? bias[col + 1] : 0.f;
#pragma unroll
            for (int hrow = 0; hrow < 2; hrow++) {
                int row = m0 + wm * ROWS_W + mt * 16 + gq + hrow * 8;
                if (row < Mlim) {
                    size_t ob = (size_t)row * 256 + col;
                    if (SPLIT) {
                        float v0 = fast_tanh(acc[mt][nt][2 * hrow + 0] + b0);
                        float v1 = fast_tanh(acc[mt][nt][2 * hrow + 1] + b1);
                        __nv_bfloat16 h0 = __float2bfloat16(v0);
                        __nv_bfloat16 h1 = __float2bfloat16(v1);
                        __nv_bfloat162 ph; ph.x = h0; ph.y = h1;
                        __nv_bfloat162 pl;
                        pl.x = __float2bfloat16(v0 - __bfloat162float(h0));
                        pl.y = __float2bfloat16(v1 - __bfloat162float(h1));
                        *(__nv_bfloat162*)(ohi + ob) = ph;
                        *(__nv_bfloat162*)(olo + ob) = pl;
                    } else {
                        float2 o;
                        o.x = acc[mt][nt][2 * hrow + 0];
                        o.y = acc[mt][nt][2 * hrow + 1];
                        *(float2*)(ofp + ob) = o;
                    }
                }
            }
        }
    }
}

// ================= host =================
extern "C" void kernel_launch(void* const* d_in, const int* in_sizes, int n_in,
                              void* d_out, int out_size) {
    (void)in_sizes; (void)n_in; (void)out_size;

    const float* x0  = (const float*)d_in[0];
    const float* x1  = (const float*)d_in[1];
    const int*   ei0 = (const int*)d_in[2];
    const int*   ei1 = (const int*)d_in[3];
    const float* W1l_0 = (const float*)d_in[4];
    const float* b1_0  = (const float*)d_in[5];
    const float* W1r_0 = (const float*)d_in[6];
    const float* W2l_0 = (const float*)d_in[7];
    const float* b2_0  = (const float*)d_in[8];
    const float* W2r_0 = (const float*)d_in[9];
    const float* W1l_1 = (const float*)d_in[10];
    const float* b1_1  = (const float*)d_in[11];
    const float* W1r_1 = (const float*)d_in[12];
    const float* W2l_1 = (const float*)d_in[13];
    const float* b2_1  = (const float*)d_in[14];
    const float* W2r_1 = (const float*)d_in[15];
    float* out = (float*)d_out;

    constexpr int SMEM = 2 * (2 * 10240 + 2 * 128 * 80);  // 81920
    cudaFuncSetAttribute((const void*)sage_mma_kernel<128, 128, 128, 128, 128, true>,
                         cudaFuncAttributeMaxDynamicSharedMemorySize, SMEM);
    cudaFuncSetAttribute((const void*)sage_mma_kernel<128, 128, 256, 256, 0, false>,
                         cudaFuncAttributeMaxDynamicSharedMemorySize, SMEM);

    int *count, *row_start, *cursor, *srcsort;
    __nv_bfloat16 *xhi, *xlo, *hhi, *hlo, *ahi, *alo, *whi, *wlo;
    float* pq;
    cudaGetSymbolAddress((void**)&count, g_count);
    cudaGetSymbolAddress((void**)&row_start, g_row_start);
    cudaGetSymbolAddress((void**)&cursor, g_cursor);
    cudaGetSymbolAddress((void**)&srcsort, g_srcsort);
    cudaGetSymbolAddress((void**)&xhi, g_xhi);
    cudaGetSymbolAddress((void**)&xlo, g_xlo);
    cudaGetSymbolAddress((void**)&hhi, g_hhi);
    cudaGetSymbolAddress((void**)&hlo, g_hlo);
    cudaGetSymbolAddress((void**)&ahi, g_ahi);
    cudaGetSymbolAddress((void**)&alo, g_alo);
    cudaGetSymbolAddress((void**)&pq, g_pq);
    cudaGetSymbolAddress((void**)&whi, g_whi);
    cudaGetSymbolAddress((void**)&wlo, g_wlo);

    // ---- upfront split: x0|x1 contiguous, 8 weight matrices ----
    SplitJobs J;
    const float* srcs[10] = {x0, x1, W1l_0, W1r_0, W2l_0, W2r_0, W1l_1, W1r_1, W2l_1, W2r_1};
    int counts[10] = {N_NODES * 128, N_NODES * 128,
                      32768, 32768, 32768, 32768, 32768, 32768, 32768, 32768};
    int cum = 0;
    for (int j = 0; j < 10; j++) {
        J.src[j] = srcs[j];
        if (j == 0)      { J.hi[j] = xhi;                          J.lo[j] = xlo; }
        else if (j == 1) { J.hi[j] = xhi + (size_t)N_NODES * 128;
                           J.lo[j] = xlo + (size_t)N_NODES * 128; }
        else             { J.hi[j] = whi + (j - 2) * 32768;
                           J.lo[j] = wlo + (j - 2) * 32768; }
        J.n4cum[j] = cum;
        cum += counts[j] / 4;
    }
    J.n4cum[10] = cum;
    split_all_kernel<<<(cum + 255) / 256, 256>>>(J);

    // ---- merged CSR ----
    cudaMemsetAsync(count, 0, NTOT * sizeof(int));
    hist_kernel<<<(ETOT + 255) / 256, 256>>>(ei0, ei1, count);
    scan_kernel<<<1, 1024>>>(count, row_start, cursor, NTOT);
    scatter_kernel<<<(ETOT + 255) / 256, 256>>>(ei0, ei1, cursor, srcsort);

    // weight slots (hi/lo indices): graph g: W1l=4g+0, W1r=4g+1, W2l=4g+2, W2r=4g+3
    GemmW W1, W2;
    for (int g = 0; g < 2; g++) {
        // layer 1: same W per y (y = output column block); K halves: agg->W1l, x->W1r
        for (int y = 0; y < 2; y++) {
            W1.b0hi[y][g] = whi + (4 * g + 0) * 32768; W1.b0lo[y][g] = wlo + (4 * g + 0) * 32768;
            W1.b1hi[y][g] = whi + (4 * g + 1) * 32768; W1.b1lo[y][g] = wlo + (4 * g + 1) * 32768;
        }
        // layer 2: y=0 -> W2l (p), y=1 -> W2r (q); K halves = cols 0..127 / 128..255
        W2.b0hi[0][g] = whi + (4 * g + 2) * 32768;       W2.b0lo[0][g] = wlo + (4 * g + 2) * 32768;
        W2.b1hi[0][g] = whi + (4 * g + 2) * 32768 + 128; W2.b1lo[0][g] = wlo + (4 * g + 2) * 32768 + 128;
        W2.b0hi[1][g] = whi + (4 * g + 3) * 32768;       W2.b0lo[1][g] = wlo + (4 * g + 3) * 32768;
        W2.b1hi[1][g] = whi + (4 * g + 3) * 32768 + 128; W2.b1lo[1][g] = wlo + (4 * g + 3) * 32768 + 128;
    }
    W1.bias[0] = b1_0; W1.bias[1] = b1_1;
    W2.bias[0] = b2_0; W2.bias[1] = b2_1;

    // ---- layer 1: agg(x) then h = tanh([agg|x] @ [W1l|W1r]^T + b1), split-stored ----
    aggregate1_kernel<<<NTOT / 2, 128>>>(xhi, xlo, row_start, srcsort, ahi, alo);
    {
        dim3 grid(M_TILES, 2, 2);
        sage_mma_kernel<128, 128, 128, 128, 128, true><<<grid, 256, SMEM>>>(
            ahi, alo, xhi, xlo, W1, hhi, hlo, nullptr);
    }

    // ---- layer 2: [p|q] = h @ [W2l^T | W2r^T]; out = tanh(mean(p) + q + b2) ----
    {
        dim3 grid(M_TILES, 2, 2);
        sage_mma_kernel<128, 128, 256, 256, 0, false><<<grid, 256, SMEM>>>(
            hhi, hlo, hhi + 128, hlo + 128, W2, nullptr, nullptr, pq);
    }
    agg_fuse2_kernel<<<NTOT / 4, 128>>>(pq, row_start, srcsort, b2_0, b2_1, out);
}